// round 3
// baseline (speedup 1.0000x reference)
#include <cuda_runtime.h>
#include <cuda_bf16.h>

#define NMAX 100000
#define EMAX 1600000
#define F1 128
#define F2 64
#define BN_EPS 1e-5f

// ---- scratch (device globals; no allocation allowed) ----
// float4-typed so 16B alignment is guaranteed for vector atomics/loads.
__device__ float  g_dis[NMAX];             // degree -> rsqrt(degree)
__device__ float4 g_H1[NMAX * 32];         // x @ W1^T           [N,128]
__device__ float4 g_AGG1[NMAX * 32];       // aggregated layer-1 [N,128]
__device__ float4 g_H2[NMAX * 16];         // relu(bn(.)) @ W2^T [N,64]
__device__ float4 g_AGG2[NMAX * 16];       // aggregated layer-2 [N,64]
__device__ float  g_sums[2 * F1];          // BN partial sums / sumsq
__device__ float  g_ss[2 * F1];            // BN scale / shift
__device__ float  g_W1T[F1 * F1];          // W1 transposed [k][col]
__device__ float  g_W2T[F1 * F2];          // W2 transposed [k][col]

// Guaranteed-global 128-bit float reduction.
__device__ __forceinline__ void red_global_f4(float4* addr, float4 v) {
    unsigned long long g = __cvta_generic_to_global(addr);
    asm volatile("red.global.add.v4.f32 [%0], {%1, %2, %3, %4};"
                 :: "l"(g), "f"(v.x), "f"(v.y), "f"(v.z), "f"(v.w)
                 : "memory");
}

// ---------------------------------------------------------------------------
// degree / norm
// ---------------------------------------------------------------------------
__global__ void k_deg_init(int n) {
    int i = blockIdx.x * blockDim.x + threadIdx.x;
    if (i < n) g_dis[i] = 1.0f;          // self-loop contributes 1 to degree
    if (i < 2 * F1) g_sums[i] = 0.0f;    // zero BN accumulators
}

__global__ void k_deg_edges(const int* __restrict__ ei, int e_cnt) {
    int e = blockIdx.x * blockDim.x + threadIdx.x;
    if (e < e_cnt) {
        int d = ei[e_cnt + e];           // edge_index[1][e]
        atomicAdd(&g_dis[d], 1.0f);
    }
}

__global__ void k_rsqrt(int n) {
    int i = blockIdx.x * blockDim.x + threadIdx.x;
    if (i < n) g_dis[i] = rsqrtf(g_dis[i]);  // deg >= 1 always (self-loop)
}

// ---------------------------------------------------------------------------
// weight transpose: W1T[k*128+c] = W1[c*128+k]; W2T[k*64+c] = W2[c*128+k]
// ---------------------------------------------------------------------------
__global__ void k_transpose(const float* __restrict__ W1,
                            const float* __restrict__ W2) {
    int idx = blockIdx.x * blockDim.x + threadIdx.x;   // over 128*128
    if (idx < F1 * F1) {
        int c = idx / F1, k = idx % F1;
        g_W1T[k * F1 + c] = W1[idx];
        if (c < F2) g_W2T[k * F2 + c] = W2[c * F1 + k];
    }
}

// ---------------------------------------------------------------------------
// GEMM1: g_H1[N,128] = x[N,128] @ W1^T  (register-blocked 8 rows x 4 cols)
// 128 threads: cg = t&31 (4 cols), rg = t>>5 (8 rows); 32 rows per block.
// ---------------------------------------------------------------------------
__global__ void __launch_bounds__(128) k_gemm1(const float* __restrict__ x, int n) {
    __shared__ float xs[32][33];
    __shared__ float ws[32][F1];
    float* H1 = (float*)g_H1;
    int row0 = blockIdx.x * 32;
    int t = threadIdx.x;
    int cg = t & 31;
    int rg = t >> 5;
    float acc[8][4];
    #pragma unroll
    for (int i = 0; i < 8; i++)
        #pragma unroll
        for (int j = 0; j < 4; j++) acc[i][j] = 0.0f;

    for (int kc = 0; kc < F1; kc += 32) {
        for (int i = t; i < 32 * 32; i += 128) {
            int r = i >> 5, k = i & 31;
            int gr = row0 + r;
            xs[r][k] = (gr < n) ? x[gr * F1 + kc + k] : 0.0f;
        }
        for (int i = t; i < 32 * F1; i += 128) {
            int k = i >> 7, c = i & 127;
            ws[k][c] = g_W1T[(kc + k) * F1 + c];
        }
        __syncthreads();
        #pragma unroll
        for (int k = 0; k < 32; k++) {
            float4 b = *(const float4*)&ws[k][4 * cg];
            #pragma unroll
            for (int i = 0; i < 8; i++) {
                float a = xs[8 * rg + i][k];
                acc[i][0] = fmaf(a, b.x, acc[i][0]);
                acc[i][1] = fmaf(a, b.y, acc[i][1]);
                acc[i][2] = fmaf(a, b.z, acc[i][2]);
                acc[i][3] = fmaf(a, b.w, acc[i][3]);
            }
        }
        __syncthreads();
    }
    #pragma unroll
    for (int i = 0; i < 8; i++) {
        int gr = row0 + 8 * rg + i;
        if (gr < n) {
            float4 v = make_float4(acc[i][0], acc[i][1], acc[i][2], acc[i][3]);
            *(float4*)&H1[gr * F1 + 4 * cg] = v;
        }
    }
}

// ---------------------------------------------------------------------------
// layer-1 aggregation init (self-loop + bias): agg[i] = h1[i]*dis[i]^2 + b1
// one thread per float4 (N*32 threads)
// ---------------------------------------------------------------------------
__global__ void k_init1(const float* __restrict__ b1, int n) {
    long long idx = (long long)blockIdx.x * blockDim.x + threadIdx.x;
    if (idx >= (long long)n * 32) return;
    int i = (int)(idx >> 5);
    int q = (int)(idx & 31);
    float w = g_dis[i]; w *= w;
    float4 v = g_H1[idx];
    float4 b = ((const float4*)b1)[q];
    float4 o = make_float4(fmaf(v.x, w, b.x), fmaf(v.y, w, b.y),
                           fmaf(v.z, w, b.z), fmaf(v.w, w, b.w));
    g_AGG1[idx] = o;
}

// ---------------------------------------------------------------------------
// layer-1 edge scatter: one warp per edge, lane handles one float4.
// ---------------------------------------------------------------------------
__global__ void __launch_bounds__(256) k_edge1(const int* __restrict__ ei, int e_cnt) {
    long long gid = (long long)blockIdx.x * blockDim.x + threadIdx.x;
    if (gid >= (long long)e_cnt * 32) return;
    int e = (int)(gid >> 5);
    int q = (int)(gid & 31);
    int s = __ldg(&ei[e]);
    int d = __ldg(&ei[e_cnt + e]);
    float w = g_dis[s] * g_dis[d];
    float4 v = g_H1[(long long)s * 32 + q];
    float4 m = make_float4(v.x * w, v.y * w, v.z * w, v.w * w);
    red_global_f4(&g_AGG1[(long long)d * 32 + q], m);
}

// ---------------------------------------------------------------------------
// BN statistics: per-column sum and sumsq over all rows
// ---------------------------------------------------------------------------
__global__ void k_bnstats(int n) {
    const float* A = (const float*)g_AGG1;
    int c = threadIdx.x;  // 128
    float s = 0.0f, s2 = 0.0f;
    for (int r = blockIdx.x; r < n; r += gridDim.x) {
        float v = A[(long long)r * F1 + c];
        s += v;
        s2 = fmaf(v, v, s2);
    }
    atomicAdd(&g_sums[c], s);
    atomicAdd(&g_sums[F1 + c], s2);
}

__global__ void k_bnfinal(const float* __restrict__ gamma,
                          const float* __restrict__ beta, int n) {
    int c = threadIdx.x;  // 128
    float inv_n = 1.0f / (float)n;
    float mean = g_sums[c] * inv_n;
    float var = g_sums[F1 + c] * inv_n - mean * mean;
    float inv = rsqrtf(var + BN_EPS);
    float sc = gamma[c] * inv;
    g_ss[c] = sc;
    g_ss[F1 + c] = beta[c] - mean * sc;
}

// ---------------------------------------------------------------------------
// GEMM2: g_H2[N,64] = relu(bn(g_AGG1)) @ W2^T
// BN + ReLU applied on operand load. 128 threads: cg=t&15 (4 cols),
// rg=t>>4 (4 rows each); 32 rows per block.
// ---------------------------------------------------------------------------
__global__ void __launch_bounds__(128) k_gemm2(int n) {
    __shared__ float xs[32][33];
    __shared__ float ws[32][F2];
    const float* A = (const float*)g_AGG1;
    float* H2 = (float*)g_H2;
    int row0 = blockIdx.x * 32;
    int t = threadIdx.x;
    int cg = t & 15;
    int rg = t >> 4;
    float acc[4][4];
    #pragma unroll
    for (int i = 0; i < 4; i++)
        #pragma unroll
        for (int j = 0; j < 4; j++) acc[i][j] = 0.0f;

    for (int kc = 0; kc < F1; kc += 32) {
        for (int i = t; i < 32 * 32; i += 128) {
            int r = i >> 5, k = i & 31;
            int gr = row0 + r;
            float v = 0.0f;
            if (gr < n) {
                int f = kc + k;
                v = fmaf(A[(long long)gr * F1 + f], g_ss[f], g_ss[F1 + f]);
                v = fmaxf(v, 0.0f);
            }
            xs[r][k] = v;
        }
        for (int i = t; i < 32 * F2; i += 128) {
            int k = i >> 6, c = i & 63;
            ws[k][c] = g_W2T[(kc + k) * F2 + c];
        }
        __syncthreads();
        #pragma unroll
        for (int k = 0; k < 32; k++) {
            float4 b = *(const float4*)&ws[k][4 * cg];
            #pragma unroll
            for (int i = 0; i < 4; i++) {
                float a = xs[4 * rg + i][k];
                acc[i][0] = fmaf(a, b.x, acc[i][0]);
                acc[i][1] = fmaf(a, b.y, acc[i][1]);
                acc[i][2] = fmaf(a, b.z, acc[i][2]);
                acc[i][3] = fmaf(a, b.w, acc[i][3]);
            }
        }
        __syncthreads();
    }
    #pragma unroll
    for (int i = 0; i < 4; i++) {
        int gr = row0 + 4 * rg + i;
        if (gr < n) {
            float4 v = make_float4(acc[i][0], acc[i][1], acc[i][2], acc[i][3]);
            *(float4*)&H2[(long long)gr * F2 + 4 * cg] = v;
        }
    }
}

// ---------------------------------------------------------------------------
// layer-2 init: agg2[i] = h2[i]*dis[i]^2 + b2  (one thread per float4, N*16)
// ---------------------------------------------------------------------------
__global__ void k_init2(const float* __restrict__ b2, int n) {
    long long idx = (long long)blockIdx.x * blockDim.x + threadIdx.x;
    if (idx >= (long long)n * 16) return;
    int i = (int)(idx >> 4);
    int q = (int)(idx & 15);
    float w = g_dis[i]; w *= w;
    float4 v = g_H2[idx];
    float4 b = ((const float4*)b2)[q];
    float4 o = make_float4(fmaf(v.x, w, b.x), fmaf(v.y, w, b.y),
                           fmaf(v.z, w, b.z), fmaf(v.w, w, b.w));
    g_AGG2[idx] = o;
}

// ---------------------------------------------------------------------------
// layer-2 edge scatter: 16 lanes per edge (64 floats = 16 float4)
// ---------------------------------------------------------------------------
__global__ void __launch_bounds__(256) k_edge2(const int* __restrict__ ei, int e_cnt) {
    long long gid = (long long)blockIdx.x * blockDim.x + threadIdx.x;
    if (gid >= (long long)e_cnt * 16) return;
    int e = (int)(gid >> 4);
    int q = (int)(gid & 15);
    int s = __ldg(&ei[e]);
    int d = __ldg(&ei[e_cnt + e]);
    float w = g_dis[s] * g_dis[d];
    float4 v = g_H2[(long long)s * 16 + q];
    float4 m = make_float4(v.x * w, v.y * w, v.z * w, v.w * w);
    red_global_f4(&g_AGG2[(long long)d * 16 + q], m);
}

// ---------------------------------------------------------------------------
// final copy: d_out <- g_AGG2
// ---------------------------------------------------------------------------
__global__ void k_copy_out(float4* __restrict__ out, int n) {
    long long idx = (long long)blockIdx.x * blockDim.x + threadIdx.x;
    if (idx < (long long)n * 16) out[idx] = g_AGG2[idx];
}

// ---------------------------------------------------------------------------
extern "C" void kernel_launch(void* const* d_in, const int* in_sizes, int n_in,
                              void* d_out, int out_size) {
    const float* x     = (const float*)d_in[0];
    const int*   ei    = (const int*)d_in[1];    // int32 on device (JAX x64 off)
    const float* W1    = (const float*)d_in[2];
    const float* b1    = (const float*)d_in[3];
    const float* gamma = (const float*)d_in[4];
    const float* beta  = (const float*)d_in[5];
    const float* W2    = (const float*)d_in[6];
    const float* b2    = (const float*)d_in[7];

    int n = in_sizes[0] / F1;       // 100000
    int e = in_sizes[1] / 2;        // 1600000

    // degree / normalization
    k_deg_init<<<(n + 255) / 256, 256>>>(n);
    k_deg_edges<<<(e + 255) / 256, 256>>>(ei, e);
    k_rsqrt<<<(n + 255) / 256, 256>>>(n);

    // weights transpose
    k_transpose<<<(F1 * F1 + 255) / 256, 256>>>(W1, W2);

    // layer 1: GEMM -> init (self-loop + bias) -> edge scatter
    k_gemm1<<<(n + 31) / 32, 128>>>(x, n);
    {
        long long tot = (long long)n * 32;
        k_init1<<<(unsigned)((tot + 255) / 256), 256>>>(b1, n);
    }
    {
        long long tot = (long long)e * 32;
        k_edge1<<<(unsigned)((tot + 255) / 256), 256>>>(ei, e);
    }

    // BN stats + params
    k_bnstats<<<512, 128>>>(n);
    k_bnfinal<<<1, 128>>>(gamma, beta, n);

    // layer 2: fused BN+ReLU GEMM -> init -> edge scatter -> copy out
    k_gemm2<<<(n + 31) / 32, 128>>>(n);
    {
        long long tot = (long long)n * 16;
        k_init2<<<(unsigned)((tot + 255) / 256), 256>>>(b2, n);
    }
    {
        long long tot = (long long)e * 16;
        k_edge2<<<(unsigned)((tot + 255) / 256), 256>>>(ei, e);
    }
    {
        long long tot = (long long)n * 16;
        k_copy_out<<<(unsigned)((tot + 255) / 256), 256>>>((float4*)d_out, n);
    }
}

// round 4
// speedup vs baseline: 1.4881x; 1.4881x over previous
#include <cuda_runtime.h>
#include <cuda_bf16.h>

#define NMAX 100000
#define EMAX 1600000
#define F1 128
#define F2 64
#define BN_EPS 1e-5f
#define SCAN_B 1024

// ---- scratch (device globals; no allocation allowed) ----
__device__ float  g_dis[NMAX];             // rsqrt(degree)
__device__ int    g_degi[NMAX];            // in-degree (edges only)
__device__ int    g_row[NMAX];             // CSR row start
__device__ int    g_cursor[NMAX];          // fill cursor
__device__ int    g_rowtmp[NMAX];          // block-local exclusive scan
__device__ int    g_bsum[128];             // scan block sums
__device__ int    g_csr[EMAX];             // src indices grouped by dst
__device__ float4 g_H1s[NMAX * 32];        // dis[r] * (x @ W1^T)      [N,128]
__device__ float4 g_AGG1[NMAX * 32];       // layer-1 aggregated       [N,128]
__device__ float4 g_H2s[NMAX * 16];        // dis[r] * (relu(bn)@W2^T) [N,64]
__device__ float  g_sums[2 * F1];          // BN sum / sumsq
__device__ float  g_ss[2 * F1];            // BN scale / shift
__device__ float  g_W1T[F1 * F1];          // W1 transposed
__device__ float  g_W2T[F1 * F2];          // W2 transposed

// ---------------------------------------------------------------------------
// init: zero degree counters and BN accumulators
// ---------------------------------------------------------------------------
__global__ void k_zero(int n) {
    int i = blockIdx.x * blockDim.x + threadIdx.x;
    if (i < n) g_degi[i] = 0;
    if (i < 2 * F1) g_sums[i] = 0.0f;
}

__global__ void k_deg_count(const int* __restrict__ ei, int e_cnt) {
    int e = blockIdx.x * blockDim.x + threadIdx.x;
    if (e < e_cnt) atomicAdd(&g_degi[ei[e_cnt + e]], 1);
}

// ---------------------------------------------------------------------------
// scan (3 stages): block-exclusive -> top-level -> finalize (+dis)
// ---------------------------------------------------------------------------
__global__ void __launch_bounds__(SCAN_B) k_scan_block(int n) {
    __shared__ int s[SCAN_B];
    int t = threadIdx.x;
    int i = blockIdx.x * SCAN_B + t;
    int v = (i < n) ? g_degi[i] : 0;
    s[t] = v;
    __syncthreads();
    for (int off = 1; off < SCAN_B; off <<= 1) {
        int a = (t >= off) ? s[t - off] : 0;
        __syncthreads();
        s[t] += a;
        __syncthreads();
    }
    if (i < n) g_rowtmp[i] = s[t] - v;          // exclusive within block
    if (t == SCAN_B - 1) g_bsum[blockIdx.x] = s[t];
}

__global__ void k_scan_top(int nb) {
    __shared__ int s[128];
    int t = threadIdx.x;                        // 128 threads
    int v = (t < nb) ? g_bsum[t] : 0;
    s[t] = v;
    __syncthreads();
    for (int off = 1; off < 128; off <<= 1) {
        int a = (t >= off) ? s[t - off] : 0;
        __syncthreads();
        s[t] += a;
        __syncthreads();
    }
    if (t < nb) g_bsum[t] = s[t] - v;           // exclusive
}

__global__ void __launch_bounds__(SCAN_B) k_scan_fin(int n) {
    int i = blockIdx.x * SCAN_B + threadIdx.x;
    if (i < n) {
        int start = g_rowtmp[i] + g_bsum[blockIdx.x];
        g_row[i] = start;
        g_cursor[i] = start;
        g_dis[i] = rsqrtf((float)(g_degi[i] + 1));   // +1 self-loop
    }
}

__global__ void k_csr_fill(const int* __restrict__ ei, int e_cnt) {
    int e = blockIdx.x * blockDim.x + threadIdx.x;
    if (e < e_cnt) {
        int s = ei[e];
        int d = ei[e_cnt + e];
        int pos = atomicAdd(&g_cursor[d], 1);
        g_csr[pos] = s;
    }
}

// ---------------------------------------------------------------------------
// weight transpose
// ---------------------------------------------------------------------------
__global__ void k_transpose(const float* __restrict__ W1,
                            const float* __restrict__ W2) {
    int idx = blockIdx.x * blockDim.x + threadIdx.x;   // over 128*128
    if (idx < F1 * F1) {
        int c = idx / F1, k = idx % F1;
        g_W1T[k * F1 + c] = W1[idx];
        if (c < F2) g_W2T[k * F2 + c] = W2[c * F1 + k];
    }
}

// ---------------------------------------------------------------------------
// GEMM1: g_H1s[r] = dis[r] * (x[r] @ W1^T)    (8 rows x 4 cols per thread)
// ---------------------------------------------------------------------------
__global__ void __launch_bounds__(128) k_gemm1(const float* __restrict__ x, int n) {
    __shared__ float xs[32][33];
    __shared__ float ws[32][F1];
    float* H1 = (float*)g_H1s;
    int row0 = blockIdx.x * 32;
    int t = threadIdx.x;
    int cg = t & 31;
    int rg = t >> 5;
    float acc[8][4];
    #pragma unroll
    for (int i = 0; i < 8; i++)
        #pragma unroll
        for (int j = 0; j < 4; j++) acc[i][j] = 0.0f;

    for (int kc = 0; kc < F1; kc += 32) {
        for (int i = t; i < 32 * 32; i += 128) {
            int r = i >> 5, k = i & 31;
            int gr = row0 + r;
            xs[r][k] = (gr < n) ? x[gr * F1 + kc + k] : 0.0f;
        }
        for (int i = t; i < 32 * F1; i += 128) {
            int k = i >> 7, c = i & 127;
            ws[k][c] = g_W1T[(kc + k) * F1 + c];
        }
        __syncthreads();
        #pragma unroll
        for (int k = 0; k < 32; k++) {
            float4 b = *(const float4*)&ws[k][4 * cg];
            #pragma unroll
            for (int i = 0; i < 8; i++) {
                float a = xs[8 * rg + i][k];
                acc[i][0] = fmaf(a, b.x, acc[i][0]);
                acc[i][1] = fmaf(a, b.y, acc[i][1]);
                acc[i][2] = fmaf(a, b.z, acc[i][2]);
                acc[i][3] = fmaf(a, b.w, acc[i][3]);
            }
        }
        __syncthreads();
    }
    #pragma unroll
    for (int i = 0; i < 8; i++) {
        int gr = row0 + 8 * rg + i;
        if (gr < n) {
            float w = g_dis[gr];
            float4 v = make_float4(acc[i][0] * w, acc[i][1] * w,
                                   acc[i][2] * w, acc[i][3] * w);
            *(float4*)&H1[gr * F1 + 4 * cg] = v;
        }
    }
}

// ---------------------------------------------------------------------------
// layer-1 pull aggregation: warp per node; fused self-loop + bias + BN stats
// agg[i] = dis[i] * (H1s[i] + sum_{s in N(i)} H1s[s]) + b1
// ---------------------------------------------------------------------------
__global__ void __launch_bounds__(256) k_agg1(const float* __restrict__ b1, int n) {
    __shared__ float ssum[F1];
    __shared__ float ssq[F1];
    int t = threadIdx.x;
    if (t < F1) { ssum[t] = 0.0f; ssq[t] = 0.0f; }
    __syncthreads();

    int warp = t >> 5, lane = t & 31;
    int i = blockIdx.x * 8 + warp;
    if (i < n) {
        int start = g_row[i];
        int deg   = g_degi[i];
        int endj  = start + deg;
        float4 acc = g_H1s[i * 32 + lane];       // self-loop term
        int j = start;
        for (; j + 3 < endj; j += 4) {
            int s0 = g_csr[j], s1 = g_csr[j + 1], s2 = g_csr[j + 2], s3 = g_csr[j + 3];
            float4 v0 = g_H1s[s0 * 32 + lane];
            float4 v1 = g_H1s[s1 * 32 + lane];
            float4 v2 = g_H1s[s2 * 32 + lane];
            float4 v3 = g_H1s[s3 * 32 + lane];
            acc.x += v0.x + v1.x + v2.x + v3.x;
            acc.y += v0.y + v1.y + v2.y + v3.y;
            acc.z += v0.z + v1.z + v2.z + v3.z;
            acc.w += v0.w + v1.w + v2.w + v3.w;
        }
        for (; j < endj; j++) {
            float4 v = g_H1s[g_csr[j] * 32 + lane];
            acc.x += v.x; acc.y += v.y; acc.z += v.z; acc.w += v.w;
        }
        float di = g_dis[i];
        float4 b = ((const float4*)b1)[lane];
        float4 r = make_float4(fmaf(acc.x, di, b.x), fmaf(acc.y, di, b.y),
                               fmaf(acc.z, di, b.z), fmaf(acc.w, di, b.w));
        g_AGG1[i * 32 + lane] = r;
        int c = 4 * lane;
        atomicAdd(&ssum[c + 0], r.x); atomicAdd(&ssq[c + 0], r.x * r.x);
        atomicAdd(&ssum[c + 1], r.y); atomicAdd(&ssq[c + 1], r.y * r.y);
        atomicAdd(&ssum[c + 2], r.z); atomicAdd(&ssq[c + 2], r.z * r.z);
        atomicAdd(&ssum[c + 3], r.w); atomicAdd(&ssq[c + 3], r.w * r.w);
    }
    __syncthreads();
    if (t < F1) {
        atomicAdd(&g_sums[t], ssum[t]);
        atomicAdd(&g_sums[F1 + t], ssq[t]);
    }
}

// ---------------------------------------------------------------------------
// BN params
// ---------------------------------------------------------------------------
__global__ void k_bnfinal(const float* __restrict__ gamma,
                          const float* __restrict__ beta, int n) {
    int c = threadIdx.x;  // 128
    float inv_n = 1.0f / (float)n;
    float mean = g_sums[c] * inv_n;
    float var = g_sums[F1 + c] * inv_n - mean * mean;
    float inv = rsqrtf(var + BN_EPS);
    float sc = gamma[c] * inv;
    g_ss[c] = sc;
    g_ss[F1 + c] = beta[c] - mean * sc;
}

// ---------------------------------------------------------------------------
// GEMM2: g_H2s[r] = dis[r] * (relu(bn(AGG1[r])) @ W2^T)
// ---------------------------------------------------------------------------
__global__ void __launch_bounds__(128) k_gemm2(int n) {
    __shared__ float xs[32][33];
    __shared__ float ws[32][F2];
    const float* A = (const float*)g_AGG1;
    float* H2 = (float*)g_H2s;
    int row0 = blockIdx.x * 32;
    int t = threadIdx.x;
    int cg = t & 15;
    int rg = t >> 4;
    float acc[4][4];
    #pragma unroll
    for (int i = 0; i < 4; i++)
        #pragma unroll
        for (int j = 0; j < 4; j++) acc[i][j] = 0.0f;

    for (int kc = 0; kc < F1; kc += 32) {
        for (int i = t; i < 32 * 32; i += 128) {
            int r = i >> 5, k = i & 31;
            int gr = row0 + r;
            float v = 0.0f;
            if (gr < n) {
                int f = kc + k;
                v = fmaf(A[gr * F1 + f], g_ss[f], g_ss[F1 + f]);
                v = fmaxf(v, 0.0f);
            }
            xs[r][k] = v;
        }
        for (int i = t; i < 32 * F2; i += 128) {
            int k = i >> 6, c = i & 63;
            ws[k][c] = g_W2T[(kc + k) * F2 + c];
        }
        __syncthreads();
        #pragma unroll
        for (int k = 0; k < 32; k++) {
            float4 b = *(const float4*)&ws[k][4 * cg];
            #pragma unroll
            for (int i = 0; i < 4; i++) {
                float a = xs[4 * rg + i][k];
                acc[i][0] = fmaf(a, b.x, acc[i][0]);
                acc[i][1] = fmaf(a, b.y, acc[i][1]);
                acc[i][2] = fmaf(a, b.z, acc[i][2]);
                acc[i][3] = fmaf(a, b.w, acc[i][3]);
            }
        }
        __syncthreads();
    }
    #pragma unroll
    for (int i = 0; i < 4; i++) {
        int gr = row0 + 4 * rg + i;
        if (gr < n) {
            float w = g_dis[gr];
            float4 v = make_float4(acc[i][0] * w, acc[i][1] * w,
                                   acc[i][2] * w, acc[i][3] * w);
            *(float4*)&H2[gr * F2 + 4 * cg] = v;
        }
    }
}

// ---------------------------------------------------------------------------
// layer-2 pull aggregation: half-warp per node, writes d_out directly
// out[i] = dis[i] * (H2s[i] + sum_{s in N(i)} H2s[s]) + b2
// ---------------------------------------------------------------------------
__global__ void __launch_bounds__(256) k_agg2(const float* __restrict__ b2, int n,
                                              float4* __restrict__ out) {
    int t = threadIdx.x;
    int warp = t >> 5, lane = t & 31;
    int sub = lane >> 4, q = lane & 15;
    int i = blockIdx.x * 16 + warp * 2 + sub;
    if (i >= n) return;
    int start = g_row[i];
    int deg   = g_degi[i];
    int endj  = start + deg;
    float4 acc = g_H2s[i * 16 + q];              // self-loop term
    int j = start;
    for (; j + 3 < endj; j += 4) {
        int s0 = g_csr[j], s1 = g_csr[j + 1], s2 = g_csr[j + 2], s3 = g_csr[j + 3];
        float4 v0 = g_H2s[s0 * 16 + q];
        float4 v1 = g_H2s[s1 * 16 + q];
        float4 v2 = g_H2s[s2 * 16 + q];
        float4 v3 = g_H2s[s3 * 16 + q];
        acc.x += v0.x + v1.x + v2.x + v3.x;
        acc.y += v0.y + v1.y + v2.y + v3.y;
        acc.z += v0.z + v1.z + v2.z + v3.z;
        acc.w += v0.w + v1.w + v2.w + v3.w;
    }
    for (; j < endj; j++) {
        float4 v = g_H2s[g_csr[j] * 16 + q];
        acc.x += v.x; acc.y += v.y; acc.z += v.z; acc.w += v.w;
    }
    float di = g_dis[i];
    float4 b = ((const float4*)b2)[q];
    out[i * 16 + q] = make_float4(fmaf(acc.x, di, b.x), fmaf(acc.y, di, b.y),
                                  fmaf(acc.z, di, b.z), fmaf(acc.w, di, b.w));
}

// ---------------------------------------------------------------------------
extern "C" void kernel_launch(void* const* d_in, const int* in_sizes, int n_in,
                              void* d_out, int out_size) {
    const float* x     = (const float*)d_in[0];
    const int*   ei    = (const int*)d_in[1];
    const float* W1    = (const float*)d_in[2];
    const float* b1    = (const float*)d_in[3];
    const float* gamma = (const float*)d_in[4];
    const float* beta  = (const float*)d_in[5];
    const float* W2    = (const float*)d_in[6];
    const float* b2    = (const float*)d_in[7];

    int n = in_sizes[0] / F1;       // 100000
    int e = in_sizes[1] / 2;        // 1600000
    int nb = (n + SCAN_B - 1) / SCAN_B;

    // CSR build + normalization
    k_zero<<<(n + 255) / 256, 256>>>(n);
    k_deg_count<<<(e + 255) / 256, 256>>>(ei, e);
    k_scan_block<<<nb, SCAN_B>>>(n);
    k_scan_top<<<1, 128>>>(nb);
    k_scan_fin<<<nb, SCAN_B>>>(n);
    k_csr_fill<<<(e + 255) / 256, 256>>>(ei, e);

    // weights transpose
    k_transpose<<<(F1 * F1 + 255) / 256, 256>>>(W1, W2);

    // layer 1
    k_gemm1<<<(n + 31) / 32, 128>>>(x, n);
    k_agg1<<<(n + 7) / 8, 256>>>(b1, n);

    // BN
    k_bnfinal<<<1, 128>>>(gamma, beta, n);

    // layer 2
    k_gemm2<<<(n + 31) / 32, 128>>>(n);
    k_agg2<<<(n + 15) / 16, 256>>>(b2, n, (float4*)d_out);
}

// round 5
// speedup vs baseline: 1.6974x; 1.1407x over previous
#include <cuda_runtime.h>
#include <cuda_bf16.h>

#define NMAX 100000
#define EMAX 1600000
#define F1 128
#define F2 64
#define BN_EPS 1e-5f
#define SCAN_B 1024

// ---- scratch (device globals; no allocation allowed) ----
__device__ float  g_dis[NMAX];             // rsqrt(degree)
__device__ int    g_degi[NMAX];            // in-degree (edges only)
__device__ int    g_row[NMAX];             // CSR row start
__device__ int    g_cursor[NMAX];          // fill cursor
__device__ int    g_rowtmp[NMAX];          // block-local exclusive scan
__device__ int    g_bsum[128];             // scan block sums
__device__ int    g_csr[EMAX];             // src indices grouped by dst
__device__ float4 g_H1s[NMAX * 32];        // dis[r] * (x @ W1^T)      [N,128]
__device__ float4 g_AGG1[NMAX * 32];       // layer-1 aggregated       [N,128]
__device__ float4 g_H2s[NMAX * 16];        // dis[r] * (relu(bn)@W2^T) [N,64]
__device__ float  g_sums[2 * F1];          // BN sum / sumsq
__device__ float  g_ss[2 * F1];            // BN scale / shift
__device__ float  g_W1T[F1 * F1];          // W1 transposed [k][c]
__device__ float  g_W2T[F1 * F2];          // W2 transposed [k][c]

// ---- tf32 helpers ----
__device__ __forceinline__ unsigned f2tf32(float f) {
    unsigned r;
    asm("cvt.rna.tf32.f32 %0, %1;" : "=r"(r) : "f"(f));
    return r;
}
__device__ __forceinline__ void split_tf32(float f, unsigned& hi, unsigned& lo) {
    hi = f2tf32(f);
    lo = f2tf32(f - __uint_as_float(hi));
}
__device__ __forceinline__ void mma_tf32(float* d, const unsigned* a, const unsigned* b) {
    asm volatile(
        "mma.sync.aligned.m16n8k8.row.col.f32.tf32.tf32.f32 "
        "{%0,%1,%2,%3}, {%4,%5,%6,%7}, {%8,%9}, {%0,%1,%2,%3};"
        : "+f"(d[0]), "+f"(d[1]), "+f"(d[2]), "+f"(d[3])
        : "r"(a[0]), "r"(a[1]), "r"(a[2]), "r"(a[3]), "r"(b[0]), "r"(b[1]));
}

// ---------------------------------------------------------------------------
// init / degree / scan / CSR fill
// ---------------------------------------------------------------------------
__global__ void k_zero(int n) {
    int i = blockIdx.x * blockDim.x + threadIdx.x;
    if (i < n) g_degi[i] = 0;
    if (i < 2 * F1) g_sums[i] = 0.0f;
}

__global__ void k_deg_count(const int* __restrict__ ei, int e_cnt) {
    int e = blockIdx.x * blockDim.x + threadIdx.x;
    if (e < e_cnt) atomicAdd(&g_degi[ei[e_cnt + e]], 1);
}

__global__ void __launch_bounds__(SCAN_B) k_scan_block(int n) {
    __shared__ int s[SCAN_B];
    int t = threadIdx.x;
    int i = blockIdx.x * SCAN_B + t;
    int v = (i < n) ? g_degi[i] : 0;
    s[t] = v;
    __syncthreads();
    for (int off = 1; off < SCAN_B; off <<= 1) {
        int a = (t >= off) ? s[t - off] : 0;
        __syncthreads();
        s[t] += a;
        __syncthreads();
    }
    if (i < n) g_rowtmp[i] = s[t] - v;
    if (t == SCAN_B - 1) g_bsum[blockIdx.x] = s[t];
}

__global__ void k_scan_top(int nb) {
    __shared__ int s[128];
    int t = threadIdx.x;
    int v = (t < nb) ? g_bsum[t] : 0;
    s[t] = v;
    __syncthreads();
    for (int off = 1; off < 128; off <<= 1) {
        int a = (t >= off) ? s[t - off] : 0;
        __syncthreads();
        s[t] += a;
        __syncthreads();
    }
    if (t < nb) g_bsum[t] = s[t] - v;
}

__global__ void __launch_bounds__(SCAN_B) k_scan_fin(int n) {
    int i = blockIdx.x * SCAN_B + threadIdx.x;
    if (i < n) {
        int start = g_rowtmp[i] + g_bsum[blockIdx.x];
        g_row[i] = start;
        g_cursor[i] = start;
        g_dis[i] = rsqrtf((float)(g_degi[i] + 1));
    }
}

__global__ void k_csr_fill(const int* __restrict__ ei, int e_cnt) {
    int e = blockIdx.x * blockDim.x + threadIdx.x;
    if (e < e_cnt) {
        int s = ei[e];
        int d = ei[e_cnt + e];
        int pos = atomicAdd(&g_cursor[d], 1);
        g_csr[pos] = s;
    }
}

// ---------------------------------------------------------------------------
// weight transpose: W1T[k][c] = W1[c][k]; W2T[k][c] = W2[c][k]
// ---------------------------------------------------------------------------
__global__ void k_transpose(const float* __restrict__ W1,
                            const float* __restrict__ W2) {
    int idx = blockIdx.x * blockDim.x + threadIdx.x;
    if (idx < F1 * F1) {
        int c = idx / F1, k = idx % F1;
        g_W1T[k * F1 + c] = W1[idx];
        if (c < F2) g_W2T[k * F2 + c] = W2[c * F1 + k];
    }
}

// ---------------------------------------------------------------------------
// GEMM1 (tf32 mma, 3-pass split): g_H1s = dis .* (x @ W1^T)
// 256 threads, tile 128 rows x 128 cols. Warp w: rows 32*(w>>1), cols 64*(w&1).
// ---------------------------------------------------------------------------
__global__ void __launch_bounds__(256) k_gemm1(const float* __restrict__ x, int n) {
    __shared__ float xs[128][36];   // (4r+k)%32 bank-distinct for frag loads
    __shared__ float ws[32][136];   // (8k+c)%32 bank-distinct
    int t = threadIdx.x;
    int w = t >> 5, lane = t & 31;
    int gid = lane >> 2, tig = lane & 3;
    int rbase = (w >> 1) * 32;
    int cbase = (w & 1) * 64;
    int row0 = blockIdx.x * 128;

    float acc[2][8][4];
    #pragma unroll
    for (int m = 0; m < 2; m++)
        #pragma unroll
        for (int nt = 0; nt < 8; nt++)
            #pragma unroll
            for (int j = 0; j < 4; j++) acc[m][nt][j] = 0.0f;

    for (int kc = 0; kc < F1; kc += 32) {
        // stage x chunk [128 rows x 32 k]
        for (int i = t; i < 1024; i += 256) {
            int r = i >> 3, kq = i & 7;
            int gr = row0 + r;
            float4 v = make_float4(0.f, 0.f, 0.f, 0.f);
            if (gr < n) v = ((const float4*)x)[gr * 32 + (kc >> 2) + kq];
            *(float4*)&xs[r][kq * 4] = v;
        }
        // stage W1T chunk [32 k x 128 c]
        for (int i = t; i < 1024; i += 256) {
            int k = i >> 5, cq = i & 31;
            float4 v = *(const float4*)&g_W1T[(kc + k) * F1 + cq * 4];
            *(float4*)&ws[k][cq * 4] = v;
        }
        __syncthreads();

        #pragma unroll
        for (int ks = 0; ks < 32; ks += 8) {
            unsigned ahi[2][4], alo[2][4], bhi[8][2], blo[8][2];
            #pragma unroll
            for (int m = 0; m < 2; m++) {
                int r0 = rbase + 16 * m + gid;
                split_tf32(xs[r0][ks + tig],         ahi[m][0], alo[m][0]);
                split_tf32(xs[r0 + 8][ks + tig],     ahi[m][1], alo[m][1]);
                split_tf32(xs[r0][ks + tig + 4],     ahi[m][2], alo[m][2]);
                split_tf32(xs[r0 + 8][ks + tig + 4], ahi[m][3], alo[m][3]);
            }
            #pragma unroll
            for (int nt = 0; nt < 8; nt++) {
                int c = cbase + 8 * nt + gid;
                split_tf32(ws[ks + tig][c],     bhi[nt][0], blo[nt][0]);
                split_tf32(ws[ks + tig + 4][c], bhi[nt][1], blo[nt][1]);
            }
            #pragma unroll
            for (int m = 0; m < 2; m++)
                #pragma unroll
                for (int nt = 0; nt < 8; nt++) {
                    mma_tf32(acc[m][nt], ahi[m], bhi[nt]);
                    mma_tf32(acc[m][nt], ahi[m], blo[nt]);
                    mma_tf32(acc[m][nt], alo[m], bhi[nt]);
                }
        }
        __syncthreads();
    }

    // epilogue: scale by dis, store float2 pairs
    float* H1 = (float*)g_H1s;
    #pragma unroll
    for (int m = 0; m < 2; m++) {
        int r_lo = row0 + rbase + 16 * m + gid;
        int r_hi = r_lo + 8;
        float dlo = (r_lo < n) ? g_dis[r_lo] : 0.0f;
        float dhi = (r_hi < n) ? g_dis[r_hi] : 0.0f;
        #pragma unroll
        for (int nt = 0; nt < 8; nt++) {
            int c = cbase + 8 * nt + 2 * tig;
            if (r_lo < n)
                *(float2*)&H1[r_lo * F1 + c] =
                    make_float2(acc[m][nt][0] * dlo, acc[m][nt][1] * dlo);
            if (r_hi < n)
                *(float2*)&H1[r_hi * F1 + c] =
                    make_float2(acc[m][nt][2] * dhi, acc[m][nt][3] * dhi);
        }
    }
}

// ---------------------------------------------------------------------------
// layer-1 pull aggregation: warp per node; fused self-loop + bias + BN stats
// ---------------------------------------------------------------------------
__global__ void __launch_bounds__(256) k_agg1(const float* __restrict__ b1, int n) {
    __shared__ float ssum[F1];
    __shared__ float ssq[F1];
    int t = threadIdx.x;
    if (t < F1) { ssum[t] = 0.0f; ssq[t] = 0.0f; }
    __syncthreads();

    int warp = t >> 5, lane = t & 31;
    int i = blockIdx.x * 8 + warp;
    if (i < n) {
        int start = g_row[i];
        int deg   = g_degi[i];
        int endj  = start + deg;
        float4 acc = g_H1s[i * 32 + lane];       // self-loop term
        int j = start;
        for (; j + 3 < endj; j += 4) {
            int s0 = g_csr[j], s1 = g_csr[j + 1], s2 = g_csr[j + 2], s3 = g_csr[j + 3];
            float4 v0 = g_H1s[s0 * 32 + lane];
            float4 v1 = g_H1s[s1 * 32 + lane];
            float4 v2 = g_H1s[s2 * 32 + lane];
            float4 v3 = g_H1s[s3 * 32 + lane];
            acc.x += v0.x + v1.x + v2.x + v3.x;
            acc.y += v0.y + v1.y + v2.y + v3.y;
            acc.z += v0.z + v1.z + v2.z + v3.z;
            acc.w += v0.w + v1.w + v2.w + v3.w;
        }
        for (; j < endj; j++) {
            float4 v = g_H1s[g_csr[j] * 32 + lane];
            acc.x += v.x; acc.y += v.y; acc.z += v.z; acc.w += v.w;
        }
        float di = g_dis[i];
        float4 b = ((const float4*)b1)[lane];
        float4 r = make_float4(fmaf(acc.x, di, b.x), fmaf(acc.y, di, b.y),
                               fmaf(acc.z, di, b.z), fmaf(acc.w, di, b.w));
        g_AGG1[i * 32 + lane] = r;
        int c = 4 * lane;
        atomicAdd(&ssum[c + 0], r.x); atomicAdd(&ssq[c + 0], r.x * r.x);
        atomicAdd(&ssum[c + 1], r.y); atomicAdd(&ssq[c + 1], r.y * r.y);
        atomicAdd(&ssum[c + 2], r.z); atomicAdd(&ssq[c + 2], r.z * r.z);
        atomicAdd(&ssum[c + 3], r.w); atomicAdd(&ssq[c + 3], r.w * r.w);
    }
    __syncthreads();
    if (t < F1) {
        atomicAdd(&g_sums[t], ssum[t]);
        atomicAdd(&g_sums[F1 + t], ssq[t]);
    }
}

// ---------------------------------------------------------------------------
// BN params
// ---------------------------------------------------------------------------
__global__ void k_bnfinal(const float* __restrict__ gamma,
                          const float* __restrict__ beta, int n) {
    int c = threadIdx.x;
    float inv_n = 1.0f / (float)n;
    float mean = g_sums[c] * inv_n;
    float var = g_sums[F1 + c] * inv_n - mean * mean;
    float inv = rsqrtf(var + BN_EPS);
    float sc = gamma[c] * inv;
    g_ss[c] = sc;
    g_ss[F1 + c] = beta[c] - mean * sc;
}

// ---------------------------------------------------------------------------
// GEMM2 (tf32 mma, 3-pass): g_H2s = dis .* (relu(bn(AGG1)) @ W2^T)
// 256 threads, tile 128 rows x 64 cols. Warp w: rows 16*w, all 64 cols.
// ---------------------------------------------------------------------------
__global__ void __launch_bounds__(256) k_gemm2(int n) {
    __shared__ float xs[128][36];
    __shared__ float ws[32][72];
    const float* A = (const float*)g_AGG1;
    int t = threadIdx.x;
    int w = t >> 5, lane = t & 31;
    int gid = lane >> 2, tig = lane & 3;
    int rbase = w * 16;
    int row0 = blockIdx.x * 128;

    float acc[8][4];
    #pragma unroll
    for (int nt = 0; nt < 8; nt++)
        #pragma unroll
        for (int j = 0; j < 4; j++) acc[nt][j] = 0.0f;

    for (int kc = 0; kc < F1; kc += 32) {
        // stage bn+relu(AGG1) chunk [128 x 32]
        for (int i = t; i < 1024; i += 256) {
            int r = i >> 3, kq = i & 7;
            int gr = row0 + r;
            float4 v = make_float4(0.f, 0.f, 0.f, 0.f);
            if (gr < n) {
                int f = kc + kq * 4;
                float4 a = ((const float4*)A)[gr * 32 + (kc >> 2) + kq];
                float4 sc = *(const float4*)&g_ss[f];
                float4 sh = *(const float4*)&g_ss[F1 + f];
                v.x = fmaxf(fmaf(a.x, sc.x, sh.x), 0.0f);
                v.y = fmaxf(fmaf(a.y, sc.y, sh.y), 0.0f);
                v.z = fmaxf(fmaf(a.z, sc.z, sh.z), 0.0f);
                v.w = fmaxf(fmaf(a.w, sc.w, sh.w), 0.0f);
            }
            *(float4*)&xs[r][kq * 4] = v;
        }
        // stage W2T chunk [32 k x 64 c]
        for (int i = t; i < 512; i += 256) {
            int k = i >> 4, cq = i & 15;
            float4 v = *(const float4*)&g_W2T[(kc + k) * F2 + cq * 4];
            *(float4*)&ws[k][cq * 4] = v;
        }
        __syncthreads();

        #pragma unroll
        for (int ks = 0; ks < 32; ks += 8) {
            unsigned ahi[4], alo[4], bhi[8][2], blo[8][2];
            {
                int r0 = rbase + gid;
                split_tf32(xs[r0][ks + tig],         ahi[0], alo[0]);
                split_tf32(xs[r0 + 8][ks + tig],     ahi[1], alo[1]);
                split_tf32(xs[r0][ks + tig + 4],     ahi[2], alo[2]);
                split_tf32(xs[r0 + 8][ks + tig + 4], ahi[3], alo[3]);
            }
            #pragma unroll
            for (int nt = 0; nt < 8; nt++) {
                int c = 8 * nt + gid;
                split_tf32(ws[ks + tig][c],     bhi[nt][0], blo[nt][0]);
                split_tf32(ws[ks + tig + 4][c], bhi[nt][1], blo[nt][1]);
            }
            #pragma unroll
            for (int nt = 0; nt < 8; nt++) {
                mma_tf32(acc[nt], ahi, bhi[nt]);
                mma_tf32(acc[nt], ahi, blo[nt]);
                mma_tf32(acc[nt], alo, bhi[nt]);
            }
        }
        __syncthreads();
    }

    float* H2 = (float*)g_H2s;
    int r_lo = row0 + rbase + gid;
    int r_hi = r_lo + 8;
    float dlo = (r_lo < n) ? g_dis[r_lo] : 0.0f;
    float dhi = (r_hi < n) ? g_dis[r_hi] : 0.0f;
    #pragma unroll
    for (int nt = 0; nt < 8; nt++) {
        int c = 8 * nt + 2 * tig;
        if (r_lo < n)
            *(float2*)&H2[r_lo * F2 + c] =
                make_float2(acc[nt][0] * dlo, acc[nt][1] * dlo);
        if (r_hi < n)
            *(float2*)&H2[r_hi * F2 + c] =
                make_float2(acc[nt][2] * dhi, acc[nt][3] * dhi);
    }
}

// ---------------------------------------------------------------------------
// layer-2 pull aggregation: half-warp per node, writes d_out directly
// ---------------------------------------------------------------------------
__global__ void __launch_bounds__(256) k_agg2(const float* __restrict__ b2, int n,
                                              float4* __restrict__ out) {
    int t = threadIdx.x;
    int warp = t >> 5, lane = t & 31;
    int sub = lane >> 4, q = lane & 15;
    int i = blockIdx.x * 16 + warp * 2 + sub;
    if (i >= n) return;
    int start = g_row[i];
    int deg   = g_degi[i];
    int endj  = start + deg;
    float4 acc = g_H2s[i * 16 + q];              // self-loop term
    int j = start;
    for (; j + 3 < endj; j += 4) {
        int s0 = g_csr[j], s1 = g_csr[j + 1], s2 = g_csr[j + 2], s3 = g_csr[j + 3];
        float4 v0 = g_H2s[s0 * 16 + q];
        float4 v1 = g_H2s[s1 * 16 + q];
        float4 v2 = g_H2s[s2 * 16 + q];
        float4 v3 = g_H2s[s3 * 16 + q];
        acc.x += v0.x + v1.x + v2.x + v3.x;
        acc.y += v0.y + v1.y + v2.y + v3.y;
        acc.z += v0.z + v1.z + v2.z + v3.z;
        acc.w += v0.w + v1.w + v2.w + v3.w;
    }
    for (; j < endj; j++) {
        float4 v = g_H2s[g_csr[j] * 16 + q];
        acc.x += v.x; acc.y += v.y; acc.z += v.z; acc.w += v.w;
    }
    float di = g_dis[i];
    float4 b = ((const float4*)b2)[q];
    out[i * 16 + q] = make_float4(fmaf(acc.x, di, b.x), fmaf(acc.y, di, b.y),
                                  fmaf(acc.z, di, b.z), fmaf(acc.w, di, b.w));
}

// ---------------------------------------------------------------------------
extern "C" void kernel_launch(void* const* d_in, const int* in_sizes, int n_in,
                              void* d_out, int out_size) {
    const float* x     = (const float*)d_in[0];
    const int*   ei    = (const int*)d_in[1];
    const float* W1    = (const float*)d_in[2];
    const float* b1    = (const float*)d_in[3];
    const float* gamma = (const float*)d_in[4];
    const float* beta  = (const float*)d_in[5];
    const float* W2    = (const float*)d_in[6];
    const float* b2    = (const float*)d_in[7];

    int n = in_sizes[0] / F1;       // 100000
    int e = in_sizes[1] / 2;        // 1600000
    int nb = (n + SCAN_B - 1) / SCAN_B;

    // CSR build + normalization
    k_zero<<<(n + 255) / 256, 256>>>(n);
    k_deg_count<<<(e + 255) / 256, 256>>>(ei, e);
    k_scan_block<<<nb, SCAN_B>>>(n);
    k_scan_top<<<1, 128>>>(nb);
    k_scan_fin<<<nb, SCAN_B>>>(n);
    k_csr_fill<<<(e + 255) / 256, 256>>>(ei, e);

    // weights transpose
    k_transpose<<<(F1 * F1 + 255) / 256, 256>>>(W1, W2);

    // layer 1
    k_gemm1<<<(n + 127) / 128, 256>>>(x, n);
    k_agg1<<<(n + 7) / 8, 256>>>(b1, n);

    // BN
    k_bnfinal<<<1, 128>>>(gamma, beta, n);

    // layer 2
    k_gemm2<<<(n + 127) / 128, 256>>>(n);
    k_agg2<<<(n + 15) / 16, 256>>>(b2, n, (float4*)d_out);
}

// round 6
// speedup vs baseline: 2.2651x; 1.3344x over previous
#include <cuda_runtime.h>
#include <cuda_fp16.h>

#define NMAX 100000
#define EMAX 1600000
#define F1 128
#define F2 64
#define BN_EPS 1e-5f
#define SCAN_B 1024
#define BN_GRID 1024

// ---- scratch (device globals; no allocation allowed) ----
__device__ float  g_dis[NMAX];             // rsqrt(degree)
__device__ int    g_degi[NMAX];            // in-degree (edges only)
__device__ int    g_row[NMAX];             // CSR row start
__device__ int    g_cursor[NMAX];          // fill cursor
__device__ int    g_rowtmp[NMAX];          // block-local exclusive scan
__device__ int    g_bsum[128];             // scan block sums
__device__ int    g_csr[EMAX];             // src indices grouped by dst
__device__ uint4  g_H1h[NMAX * 16];        // fp16 dis*(x@W1^T)        [N,128] (256B/row)
__device__ float4 g_AGG1[NMAX * 32];       // layer-1 aggregated fp32  [N,128]
__device__ uint4  g_H2h[NMAX * 8];         // fp16 dis*(relu(bn)@W2^T) [N,64]  (128B/row)
__device__ float  g_sums[2 * F1];          // BN sum / sumsq
__device__ float  g_ss[2 * F1];            // BN scale / shift
__device__ float  g_W1T[F1 * F1];          // W1 transposed [k][c]
__device__ float  g_W2T[F1 * F2];          // W2 transposed [k][c]

// ---- tf32 helpers ----
__device__ __forceinline__ unsigned f2tf32(float f) {
    unsigned r;
    asm("cvt.rna.tf32.f32 %0, %1;" : "=r"(r) : "f"(f));
    return r;
}
__device__ __forceinline__ void split_tf32(float f, unsigned& hi, unsigned& lo) {
    hi = f2tf32(f);
    lo = f2tf32(f - __uint_as_float(hi));
}
__device__ __forceinline__ void mma_tf32(float* d, const unsigned* a, const unsigned* b) {
    asm volatile(
        "mma.sync.aligned.m16n8k8.row.col.f32.tf32.tf32.f32 "
        "{%0,%1,%2,%3}, {%4,%5,%6,%7}, {%8,%9}, {%0,%1,%2,%3};"
        : "+f"(d[0]), "+f"(d[1]), "+f"(d[2]), "+f"(d[3])
        : "r"(a[0]), "r"(a[1]), "r"(a[2]), "r"(a[3]), "r"(b[0]), "r"(b[1]));
}

// fp16 row accumulate: acc[0..7] += unpack(u)
__device__ __forceinline__ void acc_u4(float* acc, uint4 u) {
    float2 f0 = __half22float2(*(__half2*)&u.x);
    float2 f1 = __half22float2(*(__half2*)&u.y);
    float2 f2 = __half22float2(*(__half2*)&u.z);
    float2 f3 = __half22float2(*(__half2*)&u.w);
    acc[0] += f0.x; acc[1] += f0.y;
    acc[2] += f1.x; acc[3] += f1.y;
    acc[4] += f2.x; acc[5] += f2.y;
    acc[6] += f3.x; acc[7] += f3.y;
}

// ---------------------------------------------------------------------------
// merged init: zero degrees + BN sums, transpose weights
// ---------------------------------------------------------------------------
__global__ void k_init(const float* __restrict__ W1,
                       const float* __restrict__ W2, int n) {
    int i = blockIdx.x * blockDim.x + threadIdx.x;
    if (i < n) g_degi[i] = 0;
    if (i < 2 * F1) g_sums[i] = 0.0f;
    if (i < F1 * F1) {
        int c = i / F1, k = i % F1;
        g_W1T[k * F1 + c] = W1[i];
        if (c < F2) g_W2T[k * F2 + c] = W2[c * F1 + k];
    }
}

__global__ void k_deg_count(const int* __restrict__ ei, int e_cnt) {
    int e = blockIdx.x * blockDim.x + threadIdx.x;
    if (e < e_cnt) atomicAdd(&g_degi[ei[e_cnt + e]], 1);
}

// ---------------------------------------------------------------------------
// scan (3 stages)
// ---------------------------------------------------------------------------
__global__ void __launch_bounds__(SCAN_B) k_scan_block(int n) {
    __shared__ int s[SCAN_B];
    int t = threadIdx.x;
    int i = blockIdx.x * SCAN_B + t;
    int v = (i < n) ? g_degi[i] : 0;
    s[t] = v;
    __syncthreads();
    for (int off = 1; off < SCAN_B; off <<= 1) {
        int a = (t >= off) ? s[t - off] : 0;
        __syncthreads();
        s[t] += a;
        __syncthreads();
    }
    if (i < n) g_rowtmp[i] = s[t] - v;
    if (t == SCAN_B - 1) g_bsum[blockIdx.x] = s[t];
}

__global__ void k_scan_top(int nb) {
    __shared__ int s[128];
    int t = threadIdx.x;
    int v = (t < nb) ? g_bsum[t] : 0;
    s[t] = v;
    __syncthreads();
    for (int off = 1; off < 128; off <<= 1) {
        int a = (t >= off) ? s[t - off] : 0;
        __syncthreads();
        s[t] += a;
        __syncthreads();
    }
    if (t < nb) g_bsum[t] = s[t] - v;
}

__global__ void __launch_bounds__(SCAN_B) k_scan_fin(int n) {
    int i = blockIdx.x * SCAN_B + threadIdx.x;
    if (i < n) {
        int start = g_rowtmp[i] + g_bsum[blockIdx.x];
        g_row[i] = start;
        g_cursor[i] = start;
        g_dis[i] = rsqrtf((float)(g_degi[i] + 1));
    }
}

__global__ void k_csr_fill(const int* __restrict__ ei, int e_cnt) {
    int e = blockIdx.x * blockDim.x + threadIdx.x;
    if (e < e_cnt) {
        int s = ei[e];
        int d = ei[e_cnt + e];
        int pos = atomicAdd(&g_cursor[d], 1);
        g_csr[pos] = s;
    }
}

// ---------------------------------------------------------------------------
// GEMM1 (tf32, 3-pass): H1h = fp16(dis .* (x @ W1^T))
// 256 threads, tile 128x128. Warp w: rows 32*(w>>1), cols 64*(w&1).
// ---------------------------------------------------------------------------
__global__ void __launch_bounds__(256) k_gemm1(const float* __restrict__ x, int n) {
    __shared__ float xs[128][36];
    __shared__ float ws[32][136];
    int t = threadIdx.x;
    int w = t >> 5, lane = t & 31;
    int gid = lane >> 2, tig = lane & 3;
    int rbase = (w >> 1) * 32;
    int cbase = (w & 1) * 64;
    int row0 = blockIdx.x * 128;

    float acc[2][8][4];
    #pragma unroll
    for (int m = 0; m < 2; m++)
        #pragma unroll
        for (int nt = 0; nt < 8; nt++)
            #pragma unroll
            for (int j = 0; j < 4; j++) acc[m][nt][j] = 0.0f;

    for (int kc = 0; kc < F1; kc += 32) {
        for (int i = t; i < 1024; i += 256) {
            int r = i >> 3, kq = i & 7;
            int gr = row0 + r;
            float4 v = make_float4(0.f, 0.f, 0.f, 0.f);
            if (gr < n) v = ((const float4*)x)[gr * 32 + (kc >> 2) + kq];
            *(float4*)&xs[r][kq * 4] = v;
        }
        for (int i = t; i < 1024; i += 256) {
            int k = i >> 5, cq = i & 31;
            float4 v = *(const float4*)&g_W1T[(kc + k) * F1 + cq * 4];
            *(float4*)&ws[k][cq * 4] = v;
        }
        __syncthreads();

        #pragma unroll
        for (int ks = 0; ks < 32; ks += 8) {
            unsigned ahi[2][4], alo[2][4], bhi[8][2], blo[8][2];
            #pragma unroll
            for (int m = 0; m < 2; m++) {
                int r0 = rbase + 16 * m + gid;
                split_tf32(xs[r0][ks + tig],         ahi[m][0], alo[m][0]);
                split_tf32(xs[r0 + 8][ks + tig],     ahi[m][1], alo[m][1]);
                split_tf32(xs[r0][ks + tig + 4],     ahi[m][2], alo[m][2]);
                split_tf32(xs[r0 + 8][ks + tig + 4], ahi[m][3], alo[m][3]);
            }
            #pragma unroll
            for (int nt = 0; nt < 8; nt++) {
                int c = cbase + 8 * nt + gid;
                split_tf32(ws[ks + tig][c],     bhi[nt][0], blo[nt][0]);
                split_tf32(ws[ks + tig + 4][c], bhi[nt][1], blo[nt][1]);
            }
            #pragma unroll
            for (int m = 0; m < 2; m++)
                #pragma unroll
                for (int nt = 0; nt < 8; nt++) {
                    mma_tf32(acc[m][nt], ahi[m], bhi[nt]);
                    mma_tf32(acc[m][nt], ahi[m], blo[nt]);
                    mma_tf32(acc[m][nt], alo[m], bhi[nt]);
                }
        }
        __syncthreads();
    }

    // epilogue: scale by dis, store fp16 pairs
    __half2* H1 = (__half2*)g_H1h;
    #pragma unroll
    for (int m = 0; m < 2; m++) {
        int r_lo = row0 + rbase + 16 * m + gid;
        int r_hi = r_lo + 8;
        float dlo = (r_lo < n) ? g_dis[r_lo] : 0.0f;
        float dhi = (r_hi < n) ? g_dis[r_hi] : 0.0f;
        #pragma unroll
        for (int nt = 0; nt < 8; nt++) {
            int c = cbase + 8 * nt + 2 * tig;
            if (r_lo < n)
                H1[r_lo * 64 + (c >> 1)] =
                    __floats2half2_rn(acc[m][nt][0] * dlo, acc[m][nt][1] * dlo);
            if (r_hi < n)
                H1[r_hi * 64 + (c >> 1)] =
                    __floats2half2_rn(acc[m][nt][2] * dhi, acc[m][nt][3] * dhi);
        }
    }
}

// ---------------------------------------------------------------------------
// layer-1 pull aggregation: half-warp (16 lanes) per node, fp16 gather,
// fp32 accumulate. agg[i] = dis[i]*(H1[i] + sum_{s} H1[s]) + b1
// ---------------------------------------------------------------------------
__global__ void __launch_bounds__(256) k_agg1(const float* __restrict__ b1, int n) {
    int t = threadIdx.x;
    int i = blockIdx.x * 16 + (t >> 4);
    int q = t & 15;                    // 16B chunk = 8 halfs = cols 8q..8q+7
    if (i >= n) return;
    int start = g_row[i];
    int deg   = g_degi[i];
    int endj  = start + deg;
    float acc[8] = {0, 0, 0, 0, 0, 0, 0, 0};
    acc_u4(acc, g_H1h[i * 16 + q]);    // self-loop
    int j = start;
    for (; j + 3 < endj; j += 4) {
        int s0 = __ldg(&g_csr[j]),     s1 = __ldg(&g_csr[j + 1]);
        int s2 = __ldg(&g_csr[j + 2]), s3 = __ldg(&g_csr[j + 3]);
        uint4 u0 = g_H1h[s0 * 16 + q];
        uint4 u1 = g_H1h[s1 * 16 + q];
        uint4 u2 = g_H1h[s2 * 16 + q];
        uint4 u3 = g_H1h[s3 * 16 + q];
        acc_u4(acc, u0); acc_u4(acc, u1); acc_u4(acc, u2); acc_u4(acc, u3);
    }
    for (; j < endj; j++) acc_u4(acc, g_H1h[__ldg(&g_csr[j]) * 16 + q]);

    float di = g_dis[i];
    float4 b0 = ((const float4*)b1)[2 * q];
    float4 b1v = ((const float4*)b1)[2 * q + 1];
    g_AGG1[i * 32 + 2 * q] =
        make_float4(fmaf(acc[0], di, b0.x), fmaf(acc[1], di, b0.y),
                    fmaf(acc[2], di, b0.z), fmaf(acc[3], di, b0.w));
    g_AGG1[i * 32 + 2 * q + 1] =
        make_float4(fmaf(acc[4], di, b1v.x), fmaf(acc[5], di, b1v.y),
                    fmaf(acc[6], di, b1v.z), fmaf(acc[7], di, b1v.w));
}

// ---------------------------------------------------------------------------
// BN statistics over AGG1 (L2-resident), 4-deep MLP
// ---------------------------------------------------------------------------
__global__ void k_bnstats(int n) {
    const float* A = (const float*)g_AGG1;
    int c = threadIdx.x;  // 128
    float s = 0.0f, s2 = 0.0f;
    int r = blockIdx.x;
    for (; r + 3 * BN_GRID < n; r += 4 * BN_GRID) {
        float v0 = A[(r) * F1 + c];
        float v1 = A[(r + BN_GRID) * F1 + c];
        float v2 = A[(r + 2 * BN_GRID) * F1 + c];
        float v3 = A[(r + 3 * BN_GRID) * F1 + c];
        s += v0 + v1 + v2 + v3;
        s2 = fmaf(v0, v0, s2); s2 = fmaf(v1, v1, s2);
        s2 = fmaf(v2, v2, s2); s2 = fmaf(v3, v3, s2);
    }
    for (; r < n; r += BN_GRID) {
        float v = A[r * F1 + c];
        s += v;
        s2 = fmaf(v, v, s2);
    }
    atomicAdd(&g_sums[c], s);
    atomicAdd(&g_sums[F1 + c], s2);
}

__global__ void k_bnfinal(const float* __restrict__ gamma,
                          const float* __restrict__ beta, int n) {
    int c = threadIdx.x;
    float inv_n = 1.0f / (float)n;
    float mean = g_sums[c] * inv_n;
    float var = g_sums[F1 + c] * inv_n - mean * mean;
    float inv = rsqrtf(var + BN_EPS);
    float sc = gamma[c] * inv;
    g_ss[c] = sc;
    g_ss[F1 + c] = beta[c] - mean * sc;
}

// ---------------------------------------------------------------------------
// GEMM2 (tf32, 3-pass): H2h = fp16(dis .* (relu(bn(AGG1)) @ W2^T))
// ---------------------------------------------------------------------------
__global__ void __launch_bounds__(256) k_gemm2(int n) {
    __shared__ float xs[128][36];
    __shared__ float ws[32][72];
    const float* A = (const float*)g_AGG1;
    int t = threadIdx.x;
    int w = t >> 5, lane = t & 31;
    int gid = lane >> 2, tig = lane & 3;
    int rbase = w * 16;
    int row0 = blockIdx.x * 128;

    float acc[8][4];
    #pragma unroll
    for (int nt = 0; nt < 8; nt++)
        #pragma unroll
        for (int j = 0; j < 4; j++) acc[nt][j] = 0.0f;

    for (int kc = 0; kc < F1; kc += 32) {
        for (int i = t; i < 1024; i += 256) {
            int r = i >> 3, kq = i & 7;
            int gr = row0 + r;
            float4 v = make_float4(0.f, 0.f, 0.f, 0.f);
            if (gr < n) {
                int f = kc + kq * 4;
                float4 a = ((const float4*)A)[gr * 32 + (kc >> 2) + kq];
                float4 sc = *(const float4*)&g_ss[f];
                float4 sh = *(const float4*)&g_ss[F1 + f];
                v.x = fmaxf(fmaf(a.x, sc.x, sh.x), 0.0f);
                v.y = fmaxf(fmaf(a.y, sc.y, sh.y), 0.0f);
                v.z = fmaxf(fmaf(a.z, sc.z, sh.z), 0.0f);
                v.w = fmaxf(fmaf(a.w, sc.w, sh.w), 0.0f);
            }
            *(float4*)&xs[r][kq * 4] = v;
        }
        for (int i = t; i < 512; i += 256) {
            int k = i >> 4, cq = i & 15;
            float4 v = *(const float4*)&g_W2T[(kc + k) * F2 + cq * 4];
            *(float4*)&ws[k][cq * 4] = v;
        }
        __syncthreads();

        #pragma unroll
        for (int ks = 0; ks < 32; ks += 8) {
            unsigned ahi[4], alo[4], bhi[8][2], blo[8][2];
            {
                int r0 = rbase + gid;
                split_tf32(xs[r0][ks + tig],         ahi[0], alo[0]);
                split_tf32(xs[r0 + 8][ks + tig],     ahi[1], alo[1]);
                split_tf32(xs[r0][ks + tig + 4],     ahi[2], alo[2]);
                split_tf32(xs[r0 + 8][ks + tig + 4], ahi[3], alo[3]);
            }
            #pragma unroll
            for (int nt = 0; nt < 8; nt++) {
                int c = 8 * nt + gid;
                split_tf32(ws[ks + tig][c],     bhi[nt][0], blo[nt][0]);
                split_tf32(ws[ks + tig + 4][c], bhi[nt][1], blo[nt][1]);
            }
            #pragma unroll
            for (int nt = 0; nt < 8; nt++) {
                mma_tf32(acc[nt], ahi, bhi[nt]);
                mma_tf32(acc[nt], ahi, blo[nt]);
                mma_tf32(acc[nt], alo, bhi[nt]);
            }
        }
        __syncthreads();
    }

    __half2* H2 = (__half2*)g_H2h;
    int r_lo = row0 + rbase + gid;
    int r_hi = r_lo + 8;
    float dlo = (r_lo < n) ? g_dis[r_lo] : 0.0f;
    float dhi = (r_hi < n) ? g_dis[r_hi] : 0.0f;
    #pragma unroll
    for (int nt = 0; nt < 8; nt++) {
        int c = 8 * nt + 2 * tig;
        if (r_lo < n)
            H2[r_lo * 32 + (c >> 1)] =
                __floats2half2_rn(acc[nt][0] * dlo, acc[nt][1] * dlo);
        if (r_hi < n)
            H2[r_hi * 32 + (c >> 1)] =
                __floats2half2_rn(acc[nt][2] * dhi, acc[nt][3] * dhi);
    }
}

// ---------------------------------------------------------------------------
// layer-2 pull aggregation: quarter-warp (8 lanes) per node, fp16 gather,
// writes d_out fp32 directly
// ---------------------------------------------------------------------------
__global__ void __launch_bounds__(256) k_agg2(const float* __restrict__ b2, int n,
                                              float4* __restrict__ out) {
    int t = threadIdx.x;
    int i = blockIdx.x * 32 + (t >> 3);
    int q = t & 7;                     // cols 8q..8q+7
    if (i >= n) return;
    int start = g_row[i];
    int deg   = g_degi[i];
    int endj  = start + deg;
    float acc[8] = {0, 0, 0, 0, 0, 0, 0, 0};
    acc_u4(acc, g_H2h[i * 8 + q]);     // self-loop
    int j = start;
    for (; j + 3 < endj; j += 4) {
        int s0 = __ldg(&g_csr[j]),     s1 = __ldg(&g_csr[j + 1]);
        int s2 = __ldg(&g_csr[j + 2]), s3 = __ldg(&g_csr[j + 3]);
        uint4 u0 = g_H2h[s0 * 8 + q];
        uint4 u1 = g_H2h[s1 * 8 + q];
        uint4 u2 = g_H2h[s2 * 8 + q];
        uint4 u3 = g_H2h[s3 * 8 + q];
        acc_u4(acc, u0); acc_u4(acc, u1); acc_u4(acc, u2); acc_u4(acc, u3);
    }
    for (; j < endj; j++) acc_u4(acc, g_H2h[__ldg(&g_csr[j]) * 8 + q]);

    float di = g_dis[i];
    float4 b0 = ((const float4*)b2)[2 * q];
    float4 b1v = ((const float4*)b2)[2 * q + 1];
    out[i * 16 + 2 * q] =
        make_float4(fmaf(acc[0], di, b0.x), fmaf(acc[1], di, b0.y),
                    fmaf(acc[2], di, b0.z), fmaf(acc[3], di, b0.w));
    out[i * 16 + 2 * q + 1] =
        make_float4(fmaf(acc[4], di, b1v.x), fmaf(acc[5], di, b1v.y),
                    fmaf(acc[6], di, b1v.z), fmaf(acc[7], di, b1v.w));
}

// ---------------------------------------------------------------------------
extern "C" void kernel_launch(void* const* d_in, const int* in_sizes, int n_in,
                              void* d_out, int out_size) {
    const float* x     = (const float*)d_in[0];
    const int*   ei    = (const int*)d_in[1];
    const float* W1    = (const float*)d_in[2];
    const float* b1    = (const float*)d_in[3];
    const float* gamma = (const float*)d_in[4];
    const float* beta  = (const float*)d_in[5];
    const float* W2    = (const float*)d_in[6];
    const float* b2    = (const float*)d_in[7];

    int n = in_sizes[0] / F1;       // 100000
    int e = in_sizes[1] / 2;        // 1600000
    int nb = (n + SCAN_B - 1) / SCAN_B;

    // init + CSR build
    k_init<<<(n + 255) / 256, 256>>>(W1, W2, n);
    k_deg_count<<<(e + 255) / 256, 256>>>(ei, e);
    k_scan_block<<<nb, SCAN_B>>>(n);
    k_scan_top<<<1, 128>>>(nb);
    k_scan_fin<<<nb, SCAN_B>>>(n);
    k_csr_fill<<<(e + 255) / 256, 256>>>(ei, e);

    // layer 1
    k_gemm1<<<(n + 127) / 128, 256>>>(x, n);
    k_agg1<<<(n + 15) / 16, 256>>>(b1, n);

    // BN
    k_bnstats<<<BN_GRID, 128>>>(n);
    k_bnfinal<<<1, 128>>>(gamma, beta, n);

    // layer 2
    k_gemm2<<<(n + 127) / 128, 256>>>(n);
    k_agg2<<<(n + 31) / 32, 256>>>(b2, n, (float4*)d_out);
}

// round 8
// speedup vs baseline: 2.8938x; 1.2776x over previous
#include <cuda_runtime.h>
#include <cuda_fp16.h>

#define NMAX 100000
#define EMAX 1600000
#define F1 128
#define F2 64
#define BN_EPS 1e-5f
#define SCAN_B 1024
#define BN_GRID 1024

// ---- scratch (device globals; no allocation allowed) ----
__device__ float  g_dis[NMAX];             // rsqrt(degree)
__device__ int    g_degi[NMAX];            // in-degree (edges only)
__device__ int    g_row[NMAX];             // CSR row start
__device__ int    g_cursor[NMAX];          // fill cursor
__device__ int    g_rowtmp[NMAX];          // block-local exclusive scan
__device__ int    g_bsum[128];             // scan block sums
__device__ int    g_csr[EMAX];             // src indices grouped by dst
__device__ uint4  g_H1h[NMAX * 16];        // fp16 dis*(x@W1^T)        [N,128]
__device__ float4 g_AGG1[NMAX * 32];       // layer-1 aggregated fp32  [N,128]
__device__ uint4  g_H2h[NMAX * 8];         // fp16 dis*(relu(bn)@W2^T) [N,64]
__device__ float  g_sums[2 * F1];          // BN sum / sumsq
__device__ float  g_ss[2 * F1];            // BN scale / shift
__device__ uint4  g_W1h4[F1 * F1 / 8];     // fp16 W1 row-major [c][k]; 16 uint4/row
__device__ uint4  g_W2h4[F1 * F2 / 8];     // fp16 W2 row-major [c][k]; 16 uint4/row

// ---- fp16 mma m16n8k16 (row.col, f32 accum) ----
__device__ __forceinline__ void mma_f16(float* d, const unsigned* a, const unsigned* b) {
    asm volatile(
        "mma.sync.aligned.m16n8k16.row.col.f32.f16.f16.f32 "
        "{%0,%1,%2,%3}, {%4,%5,%6,%7}, {%8,%9}, {%0,%1,%2,%3};"
        : "+f"(d[0]), "+f"(d[1]), "+f"(d[2]), "+f"(d[3])
        : "r"(a[0]), "r"(a[1]), "r"(a[2]), "r"(a[3]), "r"(b[0]), "r"(b[1]));
}

__device__ __forceinline__ unsigned pack_half2(float a, float b) {
    __half2 h = __floats2half2_rn(a, b);
    return *reinterpret_cast<unsigned*>(&h);
}

// fp16 row accumulate: acc[0..7] += unpack(u)
__device__ __forceinline__ void acc_u4(float* acc, uint4 u) {
    float2 f0 = __half22float2(*(__half2*)&u.x);
    float2 f1 = __half22float2(*(__half2*)&u.y);
    float2 f2 = __half22float2(*(__half2*)&u.z);
    float2 f3 = __half22float2(*(__half2*)&u.w);
    acc[0] += f0.x; acc[1] += f0.y;
    acc[2] += f1.x; acc[3] += f1.y;
    acc[4] += f2.x; acc[5] += f2.y;
    acc[6] += f3.x; acc[7] += f3.y;
}

// ---------------------------------------------------------------------------
// merged init: zero degrees + BN sums, convert weights to fp16
// ---------------------------------------------------------------------------
__global__ void k_init(const float* __restrict__ W1,
                       const float* __restrict__ W2, int n) {
    int i = blockIdx.x * blockDim.x + threadIdx.x;
    if (i < n) g_degi[i] = 0;
    if (i < 2 * F1) g_sums[i] = 0.0f;
    if (i < F1 * F1) ((__half*)g_W1h4)[i] = __float2half_rn(W1[i]);
    if (i < F1 * F2) ((__half*)g_W2h4)[i] = __float2half_rn(W2[i]);
}

__global__ void k_deg_count(const int* __restrict__ ei, int e_cnt) {
    int e = blockIdx.x * blockDim.x + threadIdx.x;
    if (e < e_cnt) atomicAdd(&g_degi[ei[e_cnt + e]], 1);
}

// ---------------------------------------------------------------------------
// scan (2 stages): block-exclusive -> finalize (predecessor-sum in-block)
// ---------------------------------------------------------------------------
__global__ void __launch_bounds__(SCAN_B) k_scan_block(int n) {
    __shared__ int s[SCAN_B];
    int t = threadIdx.x;
    int i = blockIdx.x * SCAN_B + t;
    int v = (i < n) ? g_degi[i] : 0;
    s[t] = v;
    __syncthreads();
    for (int off = 1; off < SCAN_B; off <<= 1) {
        int a = (t >= off) ? s[t - off] : 0;
        __syncthreads();
        s[t] += a;
        __syncthreads();
    }
    if (i < n) g_rowtmp[i] = s[t] - v;
    if (t == SCAN_B - 1) g_bsum[blockIdx.x] = s[t];
}

__global__ void __launch_bounds__(SCAN_B) k_scan_fin(int n, int nb) {
    __shared__ int wsum[32];
    int t = threadIdx.x;
    // sum of predecessor block totals
    int v = (t < nb && t < (int)blockIdx.x) ? g_bsum[t] : 0;
    for (int o = 16; o; o >>= 1) v += __shfl_down_sync(0xffffffffu, v, o);
    if ((t & 31) == 0) wsum[t >> 5] = v;
    __syncthreads();
    if (t < 32) {
        int s2 = wsum[t];
        for (int o = 16; o; o >>= 1) s2 += __shfl_down_sync(0xffffffffu, s2, o);
        if (t == 0) wsum[0] = s2;
    }
    __syncthreads();
    int off = wsum[0];
    int i = blockIdx.x * SCAN_B + t;
    if (i < n) {
        int start = g_rowtmp[i] + off;
        g_row[i] = start;
        g_cursor[i] = start;
        g_dis[i] = rsqrtf((float)(g_degi[i] + 1));
    }
}

__global__ void k_csr_fill(const int* __restrict__ ei, int e_cnt) {
    int e = blockIdx.x * blockDim.x + threadIdx.x;
    if (e < e_cnt) {
        int s = ei[e];
        int d = ei[e_cnt + e];
        int pos = atomicAdd(&g_cursor[d], 1);
        g_csr[pos] = s;
    }
}

// ---------------------------------------------------------------------------
// GEMM1 (fp16 mma): H1h = fp16(dis .* (x @ W1^T))
// 256 threads, tile 128x128. Warp w: rows 32*(w>>1), cols 64*(w&1).
// smem rows padded to 20 uints: (20*idx)%32 distinct -> conflict-free frags
// ---------------------------------------------------------------------------
__global__ void __launch_bounds__(256) k_gemm1(const float* __restrict__ x, int n) {
    __shared__ unsigned xs[128][20];   // 16 data uints (32 halfs) + pad
    __shared__ unsigned ws[128][20];   // 16 data uints (32 halfs) + pad
    int t = threadIdx.x;
    int w = t >> 5, lane = t & 31;
    int gid = lane >> 2, tig = lane & 3;
    int rbase = (w >> 1) * 32;
    int cbase = (w & 1) * 64;
    int row0 = blockIdx.x * 128;

    float acc[2][8][4];
    #pragma unroll
    for (int m = 0; m < 2; m++)
        #pragma unroll
        for (int nt = 0; nt < 8; nt++)
            #pragma unroll
            for (int j = 0; j < 4; j++) acc[m][nt][j] = 0.0f;

    for (int kc = 0; kc < F1; kc += 32) {
        // stage x chunk [128 rows x 32 k] as fp16
        for (int i = t; i < 1024; i += 256) {
            int r = i >> 3, kq = i & 7;
            int gr = row0 + r;
            float4 v = make_float4(0.f, 0.f, 0.f, 0.f);
            if (gr < n) v = ((const float4*)x)[gr * 32 + (kc >> 2) + kq];
            xs[r][kq * 2]     = pack_half2(v.x, v.y);
            xs[r][kq * 2 + 1] = pack_half2(v.z, v.w);
        }
        // stage W1h chunk [128 c x 32 k] = 128 rows x 4 uint4
        for (int i = t; i < 512; i += 256) {
            int c = i >> 2, q = i & 3;
            *(uint4*)&ws[c][q * 4] = g_W1h4[c * 16 + (kc >> 3) + q];
        }
        __syncthreads();

        #pragma unroll
        for (int ks2 = 0; ks2 < 16; ks2 += 8) {     // two k16 steps
            unsigned a[2][4], b[8][2];
            #pragma unroll
            for (int m = 0; m < 2; m++) {
                int r0 = rbase + 16 * m + gid;
                a[m][0] = xs[r0][ks2 + tig];
                a[m][1] = xs[r0 + 8][ks2 + tig];
                a[m][2] = xs[r0][ks2 + tig + 4];
                a[m][3] = xs[r0 + 8][ks2 + tig + 4];
            }
            #pragma unroll
            for (int nt = 0; nt < 8; nt++) {
                int c = cbase + 8 * nt + gid;
                b[nt][0] = ws[c][ks2 + tig];
                b[nt][1] = ws[c][ks2 + tig + 4];
            }
            #pragma unroll
            for (int m = 0; m < 2; m++)
                #pragma unroll
                for (int nt = 0; nt < 8; nt++)
                    mma_f16(acc[m][nt], a[m], b[nt]);
        }
        __syncthreads();
    }

    // epilogue: scale by dis, store fp16 pairs
    __half2* H1 = (__half2*)g_H1h;
    #pragma unroll
    for (int m = 0; m < 2; m++) {
        int r_lo = row0 + rbase + 16 * m + gid;
        int r_hi = r_lo + 8;
        float dlo = (r_lo < n) ? g_dis[r_lo] : 0.0f;
        float dhi = (r_hi < n) ? g_dis[r_hi] : 0.0f;
        #pragma unroll
        for (int nt = 0; nt < 8; nt++) {
            int c = cbase + 8 * nt + 2 * tig;
            if (r_lo < n)
                H1[r_lo * 64 + (c >> 1)] =
                    __floats2half2_rn(acc[m][nt][0] * dlo, acc[m][nt][1] * dlo);
            if (r_hi < n)
                H1[r_hi * 64 + (c >> 1)] =
                    __floats2half2_rn(acc[m][nt][2] * dhi, acc[m][nt][3] * dhi);
        }
    }
}

// ---------------------------------------------------------------------------
// layer-1 pull aggregation: half-warp (16 lanes) per node, fp16 gather,
// fp32 accumulate. agg[i] = dis[i]*(H1[i] + sum_{s} H1[s]) + b1
// ---------------------------------------------------------------------------
__global__ void __launch_bounds__(256) k_agg1(const float* __restrict__ b1, int n) {
    int t = threadIdx.x;
    int i = blockIdx.x * 16 + (t >> 4);
    int q = t & 15;                    // 16B chunk = 8 halfs = cols 8q..8q+7
    if (i >= n) return;
    int start = g_row[i];
    int deg   = g_degi[i];
    int endj  = start + deg;
    float acc[8] = {0, 0, 0, 0, 0, 0, 0, 0};
    acc_u4(acc, g_H1h[i * 16 + q]);    // self-loop
    int j = start;
    for (; j + 3 < endj; j += 4) {
        int s0 = __ldg(&g_csr[j]),     s1 = __ldg(&g_csr[j + 1]);
        int s2 = __ldg(&g_csr[j + 2]), s3 = __ldg(&g_csr[j + 3]);
        uint4 u0 = g_H1h[s0 * 16 + q];
        uint4 u1 = g_H1h[s1 * 16 + q];
        uint4 u2 = g_H1h[s2 * 16 + q];
        uint4 u3 = g_H1h[s3 * 16 + q];
        acc_u4(acc, u0); acc_u4(acc, u1); acc_u4(acc, u2); acc_u4(acc, u3);
    }
    for (; j < endj; j++) acc_u4(acc, g_H1h[__ldg(&g_csr[j]) * 16 + q]);

    float di = g_dis[i];
    float4 b0 = ((const float4*)b1)[2 * q];
    float4 b1v = ((const float4*)b1)[2 * q + 1];
    g_AGG1[i * 32 + 2 * q] =
        make_float4(fmaf(acc[0], di, b0.x), fmaf(acc[1], di, b0.y),
                    fmaf(acc[2], di, b0.z), fmaf(acc[3], di, b0.w));
    g_AGG1[i * 32 + 2 * q + 1] =
        make_float4(fmaf(acc[4], di, b1v.x), fmaf(acc[5], di, b1v.y),
                    fmaf(acc[6], di, b1v.z), fmaf(acc[7], di, b1v.w));
}

// ---------------------------------------------------------------------------
// BN statistics over AGG1 (L2-resident), 4-deep MLP
// ---------------------------------------------------------------------------
__global__ void k_bnstats(int n) {
    const float* A = (const float*)g_AGG1;
    int c = threadIdx.x;  // 128
    float s = 0.0f, s2 = 0.0f;
    int r = blockIdx.x;
    for (; r + 3 * BN_GRID < n; r += 4 * BN_GRID) {
        float v0 = A[(r) * F1 + c];
        float v1 = A[(r + BN_GRID) * F1 + c];
        float v2 = A[(r + 2 * BN_GRID) * F1 + c];
        float v3 = A[(r + 3 * BN_GRID) * F1 + c];
        s += v0 + v1 + v2 + v3;
        s2 = fmaf(v0, v0, s2); s2 = fmaf(v1, v1, s2);
        s2 = fmaf(v2, v2, s2); s2 = fmaf(v3, v3, s2);
    }
    for (; r < n; r += BN_GRID) {
        float v = A[r * F1 + c];
        s += v;
        s2 = fmaf(v, v, s2);
    }
    atomicAdd(&g_sums[c], s);
    atomicAdd(&g_sums[F1 + c], s2);
}

__global__ void k_bnfinal(const float* __restrict__ gamma,
                          const float* __restrict__ beta, int n) {
    int c = threadIdx.x;
    float inv_n = 1.0f / (float)n;
    float mean = g_sums[c] * inv_n;
    float var = g_sums[F1 + c] * inv_n - mean * mean;
    float inv = rsqrtf(var + BN_EPS);
    float sc = gamma[c] * inv;
    g_ss[c] = sc;
    g_ss[F1 + c] = beta[c] - mean * sc;
}

// ---------------------------------------------------------------------------
// GEMM2 (fp16 mma): H2h = fp16(dis .* (relu(bn(AGG1)) @ W2^T))
// 256 threads, tile 128x64. Warp w: rows 16*w, all 64 cols.
// ---------------------------------------------------------------------------
__global__ void __launch_bounds__(256) k_gemm2(int n) {
    __shared__ unsigned xs[128][20];
    __shared__ unsigned ws[64][20];
    const float* A = (const float*)g_AGG1;
    int t = threadIdx.x;
    int w = t >> 5, lane = t & 31;
    int gid = lane >> 2, tig = lane & 3;
    int rbase = w * 16;
    int row0 = blockIdx.x * 128;

    float acc[8][4];
    #pragma unroll
    for (int nt = 0; nt < 8; nt++)
        #pragma unroll
        for (int j = 0; j < 4; j++) acc[nt][j] = 0.0f;

    for (int kc = 0; kc < F1; kc += 32) {
        // stage bn+relu(AGG1) chunk as fp16
        for (int i = t; i < 1024; i += 256) {
            int r = i >> 3, kq = i & 7;
            int gr = row0 + r;
            float4 v = make_float4(0.f, 0.f, 0.f, 0.f);
            if (gr < n) {
                int f = kc + kq * 4;
                float4 a = ((const float4*)A)[gr * 32 + (kc >> 2) + kq];
                float4 sc = *(const float4*)&g_ss[f];
                float4 sh = *(const float4*)&g_ss[F1 + f];
                v.x = fmaxf(fmaf(a.x, sc.x, sh.x), 0.0f);
                v.y = fmaxf(fmaf(a.y, sc.y, sh.y), 0.0f);
                v.z = fmaxf(fmaf(a.z, sc.z, sh.z), 0.0f);
                v.w = fmaxf(fmaf(a.w, sc.w, sh.w), 0.0f);
            }
            xs[r][kq * 2]     = pack_half2(v.x, v.y);
            xs[r][kq * 2 + 1] = pack_half2(v.z, v.w);
        }
        // stage W2h chunk [64 c x 32 k] = 64 rows x 4 uint4
        if (t < 256) {
            int c = t >> 2, q = t & 3;
            *(uint4*)&ws[c][q * 4] = g_W2h4[c * 16 + (kc >> 3) + q];
        }
        __syncthreads();

        #pragma unroll
        for (int ks2 = 0; ks2 < 16; ks2 += 8) {
            unsigned a[4], b[8][2];
            {
                int r0 = rbase + gid;
                a[0] = xs[r0][ks2 + tig];
                a[1] = xs[r0 + 8][ks2 + tig];
                a[2] = xs[r0][ks2 + tig + 4];
                a[3] = xs[r0 + 8][ks2 + tig + 4];
            }
            #pragma unroll
            for (int nt = 0; nt < 8; nt++) {
                int c = 8 * nt + gid;
                b[nt][0] = ws[c][ks2 + tig];
                b[nt][1] = ws[c][ks2 + tig + 4];
            }
            #pragma unroll
            for (int nt = 0; nt < 8; nt++)
                mma_f16(acc[nt], a, b[nt]);
        }
        __syncthreads();
    }

    __half2* H2 = (__half2*)g_H2h;
    int r_lo = row0 + rbase + gid;
    int r_hi = r_lo + 8;
    float dlo = (r_lo < n) ? g_dis[r_lo] : 0.0f;
    float dhi = (r_hi < n) ? g_dis[r_hi] : 0.0f;
    #pragma unroll
    for (int nt = 0; nt < 8; nt++) {
        int c = 8 * nt + 2 * tig;
        if (r_lo < n)
            H2[r_lo * 32 + (c >> 1)] =
                __floats2half2_rn(acc[nt][0] * dlo, acc[nt][1] * dlo);
        if (r_hi < n)
            H2[r_hi * 32 + (c >> 1)] =
                __floats2half2_rn(acc[nt][2] * dhi, acc[nt][3] * dhi);
    }
}

// ---------------------------------------------------------------------------
// layer-2 pull aggregation: quarter-warp (8 lanes) per node, fp16 gather,
// writes d_out fp32 directly
// ---------------------------------------------------------------------------
__global__ void __launch_bounds__(256) k_agg2(const float* __restrict__ b2, int n,
                                              float4* __restrict__ out) {
    int t = threadIdx.x;
    int i = blockIdx.x * 32 + (t >> 3);
    int q = t & 7;                     // cols 8q..8q+7
    if (i >= n) return;
    int start = g_row[i];
    int deg   = g_degi[i];
    int endj  = start + deg;
    float acc[8] = {0, 0, 0, 0, 0, 0, 0, 0};
    acc_u4(acc, g_H2h[i * 8 + q]);     // self-loop
    int j = start;
    for (; j + 3 < endj; j += 4) {
        int s0 = __ldg(&g_csr[j]),     s1 = __ldg(&g_csr[j + 1]);
        int s2 = __ldg(&g_csr[j + 2]), s3 = __ldg(&g_csr[j + 3]);
        uint4 u0 = g_H2h[s0 * 8 + q];
        uint4 u1 = g_H2h[s1 * 8 + q];
        uint4 u2 = g_H2h[s2 * 8 + q];
        uint4 u3 = g_H2h[s3 * 8 + q];
        acc_u4(acc, u0); acc_u4(acc, u1); acc_u4(acc, u2); acc_u4(acc, u3);
    }
    for (; j < endj; j++) acc_u4(acc, g_H2h[__ldg(&g_csr[j]) * 8 + q]);

    float di = g_dis[i];
    float4 b0 = ((const float4*)b2)[2 * q];
    float4 b1v = ((const float4*)b2)[2 * q + 1];
    out[i * 16 + 2 * q] =
        make_float4(fmaf(acc[0], di, b0.x), fmaf(acc[1], di, b0.y),
                    fmaf(acc[2], di, b0.z), fmaf(acc[3], di, b0.w));
    out[i * 16 + 2 * q + 1] =
        make_float4(fmaf(acc[4], di, b1v.x), fmaf(acc[5], di, b1v.y),
                    fmaf(acc[6], di, b1v.z), fmaf(acc[7], di, b1v.w));
}

// ---------------------------------------------------------------------------
extern "C" void kernel_launch(void* const* d_in, const int* in_sizes, int n_in,
                              void* d_out, int out_size) {
    const float* x     = (const float*)d_in[0];
    const int*   ei    = (const int*)d_in[1];
    const float* W1    = (const float*)d_in[2];
    const float* b1    = (const float*)d_in[3];
    const float* gamma = (const float*)d_in[4];
    const float* beta  = (const float*)d_in[5];
    const float* W2    = (const float*)d_in[6];
    const float* b2    = (const float*)d_in[7];

    int n = in_sizes[0] / F1;       // 100000
    int e = in_sizes[1] / 2;        // 1600000
    int nb = (n + SCAN_B - 1) / SCAN_B;

    // init + CSR build
    k_init<<<(n + 255) / 256, 256>>>(W1, W2, n);
    k_deg_count<<<(e + 255) / 256, 256>>>(ei, e);
    k_scan_block<<<nb, SCAN_B>>>(n);
    k_scan_fin<<<nb, SCAN_B>>>(n, nb);
    k_csr_fill<<<(e + 255) / 256, 256>>>(ei, e);

    // layer 1
    k_gemm1<<<(n + 127) / 128, 256>>>(x, n);
    k_agg1<<<(n + 15) / 16, 256>>>(b1, n);

    // BN
    k_bnstats<<<BN_GRID, 128>>>(n);
    k_bnfinal<<<1, 128>>>(gamma, beta, n);

    // layer 2
    k_gemm2<<<(n + 127) / 128, 256>>>(n);
    k_agg2<<<(n + 31) / 32, 256>>>(b2, n, (float4*)d_out);
}